// round 3
// baseline (speedup 1.0000x reference)
#include <cuda_runtime.h>
#include <cstdint>

#define NN 8192
#define DD 128
#define CAP 352
#define NDSZ (NN * DD)

// ---------------- scratch (static device globals: no runtime allocation) ----
__device__ float g_qkv[3 * NDSZ];     // Q | K | V for current layer
__device__ float g_attn[NDSZ];        // attn @ V result
__device__ int   g_deg[NN];
__device__ int   g_nbr[(size_t)NN * CAP];

// ---------------- CSR build from bool mask (layout sniffed at runtime) ------
// Diagonal of mask is always True. Byte at offset 1*(NN+1)=8193:
//   * 1-byte bool layout: mask[1][1] == 1  -> nonzero
//   * 4-byte layout (int32 0/1 or fp32 0.0/1.0): byte 1 of a 0/1-valued word
//     is always 0x00.
// So that single byte deterministically selects the parse path.
__global__ void build_csr_kernel(const unsigned char* __restrict__ mask) {
    int row = blockIdx.x;
    __shared__ int cnt;
    if (threadIdx.x == 0) cnt = 0;
    __syncthreads();

    bool bytewise = (mask[(size_t)(NN + 1)] != 0);

    if (bytewise) {
        const uint4* mrow = (const uint4*)(mask + (size_t)row * NN);
        for (int t = threadIdx.x; t < NN / 16; t += blockDim.x) {
            uint4 v = mrow[t];
            unsigned int w[4] = {v.x, v.y, v.z, v.w};
#pragma unroll
            for (int wi = 0; wi < 4; wi++) {
                unsigned int x = w[wi];
                if (x) {
#pragma unroll
                    for (int b = 0; b < 4; b++) {
                        if ((x >> (b * 8)) & 0xFFu) {
                            int pos = atomicAdd(&cnt, 1);
                            if (pos < CAP)
                                g_nbr[(size_t)row * CAP + pos] = t * 16 + wi * 4 + b;
                        }
                    }
                }
            }
        }
    } else {
        // 4-byte elements; nonzero word == edge (covers int32 1 and fp32 1.0f)
        const uint4* mrow = (const uint4*)((const unsigned int*)mask + (size_t)row * NN);
        for (int t = threadIdx.x; t < NN / 4; t += blockDim.x) {
            uint4 v = mrow[t];
            unsigned int w[4] = {v.x, v.y, v.z, v.w};
#pragma unroll
            for (int wi = 0; wi < 4; wi++) {
                if (w[wi]) {
                    int pos = atomicAdd(&cnt, 1);
                    if (pos < CAP)
                        g_nbr[(size_t)row * CAP + pos] = t * 4 + wi;
                }
            }
        }
    }
    __syncthreads();
    if (threadIdx.x == 0) g_deg[row] = (cnt < CAP) ? cnt : CAP;
}

// ---------------- fp32 GEMM: C[M,128] = A[M,128] @ W[128,128] + bias --------
// BM=64, BN=128, BK=32, 256 threads, 8x4 microtile. blockIdx.y selects one of
// up to 3 (W, bias, C) triples so QKV runs as one launch.
__global__ __launch_bounds__(256) void gemm_kernel(
    const float* __restrict__ A,
    const float* __restrict__ W0, const float* __restrict__ W1, const float* __restrict__ W2,
    const float* __restrict__ b0, const float* __restrict__ b1, const float* __restrict__ b2,
    float* __restrict__ C0, float* __restrict__ C1, float* __restrict__ C2)
{
    const float* W    = (blockIdx.y == 0) ? W0 : (blockIdx.y == 1) ? W1 : W2;
    const float* bias = (blockIdx.y == 0) ? b0 : (blockIdx.y == 1) ? b1 : b2;
    float*       C    = (blockIdx.y == 0) ? C0 : (blockIdx.y == 1) ? C1 : C2;

    __shared__ float Ast[32][65];   // transposed A tile, padded
    __shared__ float Bs[32][128];

    int tid = threadIdx.x;
    int ty = tid >> 5;    // 0..7  -> 8 rows each
    int tx = tid & 31;    // 0..31 -> 4 cols each
    int row0 = blockIdx.x * 64;

    float acc[8][4];
#pragma unroll
    for (int r = 0; r < 8; r++)
#pragma unroll
        for (int c = 0; c < 4; c++) acc[r][c] = 0.0f;

    for (int k0 = 0; k0 < 128; k0 += 32) {
        // load A tile (64x32) transposed into Ast
#pragma unroll
        for (int i = 0; i < 2; i++) {
            int idx = tid + i * 256;          // 0..511
            int r = idx >> 3;                 // 0..63
            int kg = idx & 7;                 // *4
            float4 v = *(const float4*)(A + (size_t)(row0 + r) * 128 + k0 + kg * 4);
            Ast[kg * 4 + 0][r] = v.x;
            Ast[kg * 4 + 1][r] = v.y;
            Ast[kg * 4 + 2][r] = v.z;
            Ast[kg * 4 + 3][r] = v.w;
        }
        // load W tile (32x128)
#pragma unroll
        for (int i = 0; i < 4; i++) {
            int idx = tid + i * 256;          // 0..1023
            int kk = idx >> 5;
            int cg = idx & 31;
            *(float4*)&Bs[kk][cg * 4] =
                *(const float4*)(W + (size_t)(k0 + kk) * 128 + cg * 4);
        }
        __syncthreads();

#pragma unroll
        for (int kk = 0; kk < 32; kk++) {
            float a[8], b[4];
#pragma unroll
            for (int r = 0; r < 8; r++) a[r] = Ast[kk][ty * 8 + r];
            float4 bv = *(const float4*)&Bs[kk][tx * 4];
            b[0] = bv.x; b[1] = bv.y; b[2] = bv.z; b[3] = bv.w;
#pragma unroll
            for (int r = 0; r < 8; r++)
#pragma unroll
                for (int c = 0; c < 4; c++) acc[r][c] += a[r] * b[c];
        }
        __syncthreads();
    }

    float4 bb = *(const float4*)(bias + tx * 4);
#pragma unroll
    for (int r = 0; r < 8; r++) {
        int row = row0 + ty * 8 + r;
        float4 o;
        o.x = acc[r][0] + bb.x;
        o.y = acc[r][1] + bb.y;
        o.z = acc[r][2] + bb.z;
        o.w = acc[r][3] + bb.w;
        *(float4*)(C + (size_t)row * 128 + tx * 4) = o;
    }
}

// ---------------- sparse masked-softmax attention: one CTA (128 thr) / row --
__global__ __launch_bounds__(128) void attn_kernel(
    const float* __restrict__ Q, const float* __restrict__ K,
    const float* __restrict__ V, float* __restrict__ Out)
{
    int row = blockIdx.x;
    int tid = threadIdx.x;
    int lane = tid & 31;
    int warp = tid >> 5;

    __shared__ float qs[128];
    __shared__ int   js[CAP];
    __shared__ float ss[CAP];
    __shared__ float red_max[4];
    __shared__ float red_sum[4];
    __shared__ float bc[2];

    int deg = g_deg[row];
    qs[tid] = Q[(size_t)row * 128 + tid];
    for (int n = tid; n < deg; n += 128)
        js[n] = g_nbr[(size_t)row * CAP + n];
    __syncthreads();

    // scores: warp per neighbor (strided)
    const float scale = 0.08838834764831845f;   // 1/sqrt(128)
    float4 q4 = ((const float4*)qs)[lane];
    for (int n = warp; n < deg; n += 4) {
        int j = js[n];
        float4 k4 = *((const float4*)(K + (size_t)j * 128) + lane);
        float s = k4.x * q4.x + k4.y * q4.y + k4.z * q4.z + k4.w * q4.w;
#pragma unroll
        for (int o = 16; o; o >>= 1) s += __shfl_xor_sync(0xFFFFFFFFu, s, o);
        if (lane == 0) ss[n] = s * scale;
    }
    __syncthreads();

    // block max
    float m = -1e30f;
    for (int n = tid; n < deg; n += 128) m = fmaxf(m, ss[n]);
#pragma unroll
    for (int o = 16; o; o >>= 1) m = fmaxf(m, __shfl_xor_sync(0xFFFFFFFFu, m, o));
    if (lane == 0) red_max[warp] = m;
    __syncthreads();
    if (tid == 0)
        bc[0] = fmaxf(fmaxf(red_max[0], red_max[1]), fmaxf(red_max[2], red_max[3]));
    __syncthreads();
    m = bc[0];

    // exp + sum
    float sum = 0.0f;
    for (int n = tid; n < deg; n += 128) {
        float p = expf(ss[n] - m);
        ss[n] = p;
        sum += p;
    }
#pragma unroll
    for (int o = 16; o; o >>= 1) sum += __shfl_xor_sync(0xFFFFFFFFu, sum, o);
    if (lane == 0) red_sum[warp] = sum;
    __syncthreads();
    if (tid == 0)
        bc[1] = red_sum[0] + red_sum[1] + red_sum[2] + red_sum[3];
    __syncthreads();
    float inv_total = 1.0f / bc[1];

    // accumulate O[d] = sum_n p_n * V[j_n][d]
    float acc = 0.0f;
    for (int n = 0; n < deg; n++) {
        acc += ss[n] * V[(size_t)js[n] * 128 + tid];
    }
    Out[(size_t)row * 128 + tid] = acc * inv_total;
}

// ---------------- launch -----------------------------------------------------
extern "C" void kernel_launch(void* const* d_in, const int* in_sizes, int n_in,
                              void* d_out, int out_size)
{
    const float*         features = (const float*)d_in[0];
    const unsigned char* mask     = (const unsigned char*)d_in[1];
    const float* Wq = (const float*)d_in[2];
    const float* bq = (const float*)d_in[3];
    const float* Wk = (const float*)d_in[4];
    const float* bk = (const float*)d_in[5];
    const float* Wv = (const float*)d_in[6];
    const float* bv = (const float*)d_in[7];
    const float* Wo = (const float*)d_in[8];
    const float* bo = (const float*)d_in[9];
    float* out = (float*)d_out;

    float *qkv_p, *attn_p;
    cudaGetSymbolAddress((void**)&qkv_p, g_qkv);
    cudaGetSymbolAddress((void**)&attn_p, g_attn);
    float* Qp = qkv_p;
    float* Kp = qkv_p + NDSZ;
    float* Vp = qkv_p + 2 * (size_t)NDSZ;

    // outputs[0] = features
    cudaMemcpyAsync(out, features, (size_t)NDSZ * sizeof(float),
                    cudaMemcpyDeviceToDevice);

    build_csr_kernel<<<NN, 256>>>(mask);

    for (int l = 0; l < 2; l++) {
        const float* h = (l == 0) ? features : out + (size_t)l * NDSZ;
        const float* Wq_l = Wq + (size_t)l * DD * DD;
        const float* Wk_l = Wk + (size_t)l * DD * DD;
        const float* Wv_l = Wv + (size_t)l * DD * DD;
        const float* Wo_l = Wo + (size_t)l * DD * DD;
        const float* bq_l = bq + (size_t)l * DD;
        const float* bk_l = bk + (size_t)l * DD;
        const float* bv_l = bv + (size_t)l * DD;
        const float* bo_l = bo + (size_t)l * DD;

        // Q, K, V projections (3 GEMMs in one launch)
        gemm_kernel<<<dim3(NN / 64, 3), 256>>>(
            h, Wq_l, Wk_l, Wv_l, bq_l, bk_l, bv_l, Qp, Kp, Vp);

        // sparse masked attention
        attn_kernel<<<NN, 128>>>(Qp, Kp, Vp, attn_p);

        // output projection -> directly into d_out slot (also next layer's h)
        float* h_next = out + (size_t)(l + 1) * NDSZ;
        gemm_kernel<<<dim3(NN / 64, 1), 256>>>(
            attn_p, Wo_l, Wo_l, Wo_l, bo_l, bo_l, bo_l, h_next, h_next, h_next);
    }
}